// round 16
// baseline (speedup 1.0000x reference)
#include <cuda_runtime.h>
#include <cuda_bf16.h>
#include <math.h>
#include <stdint.h>

// ---------------------------------------------------------------------------
// B=1, D=6, H=128, W=128, C=180, NH=6, HD=30, WS=(2,8,8) -> N=128/window,
// 768 windows, SS=(1,4,4), HID=360
// ---------------------------------------------------------------------------
#define NTOK   98304
#define CD     180
#define C3     540
#define C2     360
#define NWIN   768
#define NHEAD  6
#define HDIM   30
#define NMASK  16384
#define KP1    192
#define KP2    384
#define SCALE_F 0.18257418583505536f

// ------------------------- scratch (static, no alloc) ----------------------
__device__ __nv_bfloat16 g_a1 [(size_t)NTOK * KP1];
__device__ __nv_bfloat16 g_a1m[(size_t)NTOK * KP1];
__device__ __nv_bfloat16 g_qkv_s[(size_t)NTOK * C3];
__device__ __nv_bfloat16 g_qkv_m[(size_t)NTOK * C3];
__device__ __nv_bfloat16 g_xo  [(size_t)NTOK * KP2];
__device__ float         g_x1  [(size_t)NTOK * CD];
__device__ __nv_bfloat16 g_a2  [(size_t)NTOK * KP1];
__device__ __nv_bfloat16 g_hid [(size_t)NTOK * KP2];
__device__ __nv_bfloat16 g_bm  [(size_t)NWIN * NHEAD * NMASK];  // bias+mask bf16
__device__ __nv_bfloat16 g_wqs [640 * KP1];
__device__ __nv_bfloat16 g_wqm [640 * KP1];
__device__ __nv_bfloat16 g_wpr [256 * KP2];
__device__ __nv_bfloat16 g_wmix[768 * KP1];
__device__ __nv_bfloat16 g_wf2 [256 * KP2];

__device__ __forceinline__ int win2glob(int r) {
    int w = r >> 7, n = r & 127;
    int dblk = w >> 8, hblk = (w >> 4) & 15, wblk = w & 15;
    int wd = n >> 6,  wh = (n >> 3) & 7,   ww = n & 7;
    int d = dblk * 2 + wd + 1; if (d >= 6) d -= 6;
    int hh = (hblk * 8 + wh + 4) & 127;
    int w2 = (wblk * 8 + ww + 4) & 127;
    return (d * 128 + hh) * 128 + w2;
}

__device__ __forceinline__ uint32_t smem_u32(const void* p) {
    uint32_t a;
    asm("{ .reg .u64 t; cvta.to.shared.u64 t, %1; cvt.u32.u64 %0, t; }"
        : "=r"(a) : "l"(p));
    return a;
}

#define LDMATRIX_X4(r0, r1, r2, r3, addr) \
    asm volatile("ldmatrix.sync.aligned.m8n8.x4.shared.b16 {%0,%1,%2,%3}, [%4];" \
        : "=r"(r0), "=r"(r1), "=r"(r2), "=r"(r3) : "r"(addr))

#define MMA16816(d, a, b) \
    asm volatile("mma.sync.aligned.m16n8k16.row.col.f32.bf16.bf16.f32 " \
        "{%0,%1,%2,%3}, {%4,%5,%6,%7}, {%8,%9}, {%0,%1,%2,%3};" \
        : "+f"((d)[0]), "+f"((d)[1]), "+f"((d)[2]), "+f"((d)[3]) \
        : "r"((a)[0]), "r"((a)[1]), "r"((a)[2]), "r"((a)[3]), \
          "r"((b)[0]), "r"((b)[1]))

#define CP_ASYNC16(dst, src) \
    asm volatile("cp.async.cg.shared.global [%0], [%1], 16;" :: "r"(dst), "l"(src))
#define CP_COMMIT() asm volatile("cp.async.commit_group;")
#define CP_WAIT0()  asm volatile("cp.async.wait_group 0;")
#define CP_WAIT1()  asm volatile("cp.async.wait_group 1;")
#define CP_WAIT2()  asm volatile("cp.async.wait_group 2;")

// ------------------------- merged prep kernel ------------------------------
// segments: bm(combined bias+mask) | wqsT | wqmT | wprT | wf2T | wmix | pad
#define PREP_BM   75497472
#define PREP_TOTAL (PREP_BM + 122880 + 122880 + 98304 + 98304 + 147456 + 294912)
__global__ void prep_all(const float* __restrict__ rpb, const int* __restrict__ rpi,
                         const float* __restrict__ mask,
                         const float* __restrict__ wqs, const float* __restrict__ wqm,
                         const float* __restrict__ wpr, const float* __restrict__ wf2,
                         const float* __restrict__ w11, const float* __restrict__ w12) {
    long long gidx = (long long)blockIdx.x * 256 + threadIdx.x;
    if (gidx < PREP_BM) {                                // combined bias+mask
        int wh = (int)(gidx >> 14), nm = (int)(gidx & (NMASK - 1));
        int w = wh / NHEAD, h = wh - w * NHEAD;
        g_bm[gidx] = __float2bfloat16(rpb[rpi[nm] * NHEAD + h] +
                                      mask[(size_t)w * NMASK + nm]);
        return;
    }
    int idx = (int)(gidx - PREP_BM);
    if (idx < 122880) {                                  // wqs^T (640 x 192)
        int n = idx / KP1, k = idx - n * KP1;
        g_wqs[idx] = __float2bfloat16((n < C3 && k < CD) ? wqs[(size_t)k * C3 + n] : 0.f);
        return;
    }
    idx -= 122880;
    if (idx < 122880) {                                  // wqm^T
        int n = idx / KP1, k = idx - n * KP1;
        g_wqm[idx] = __float2bfloat16((n < C3 && k < CD) ? wqm[(size_t)k * C3 + n] : 0.f);
        return;
    }
    idx -= 122880;
    if (idx < 98304) {                                   // wpr^T (256 x 384)
        int n = idx / KP2, k = idx - n * KP2;
        g_wpr[idx] = __float2bfloat16((n < CD && k < C2) ? wpr[(size_t)k * CD + n] : 0.f);
        return;
    }
    idx -= 98304;
    if (idx < 98304) {                                   // wf2^T (256 x 384)
        int n = idx / KP2, k = idx - n * KP2;
        g_wf2[idx] = __float2bfloat16((n < CD && k < C2) ? wf2[(size_t)k * CD + n] : 0.f);
        return;
    }
    idx -= 98304;
    if (idx < 147456) {                                  // wmix (768 x 192)
        int r = idx / KP1, k = idx - r * KP1;
        int n = r >> 1;
        float v = 0.f;
        if (k < CD && n < C2)
            v = (r & 1) ? w12[(size_t)k * C2 + n] : w11[(size_t)k * C2 + n];
        g_wmix[idx] = __float2bfloat16(v);
        return;
    }
    idx -= 147456;
    if (idx < 294912) {                                  // pad cols 360..383
        int r = idx / 3, s = idx - r * 3;
        uint4 z = make_uint4(0, 0, 0, 0);
        *(uint4*)(g_xo  + (size_t)r * KP2 + 360 + 8 * s) = z;
        *(uint4*)(g_hid + (size_t)r * KP2 + 360 + 8 * s) = z;
    }
}

// ------------------------- LayerNorms (warp/token, bf16 out) ---------------
__global__ void ln1_kernel(const float* __restrict__ x, const float* __restrict__ g,
                           const float* __restrict__ b, const float* __restrict__ pb) {
    int r = blockIdx.x * 8 + (threadIdx.x >> 5);
    int lane = threadIdx.x & 31;
    const float* xr = x + (size_t)win2glob(r) * CD;
    float vals[6], s = 0.f, s2 = 0.f;
#pragma unroll
    for (int i = 0; i < 6; i++) {
        int c = lane + i * 32;
        float v = (c < CD) ? xr[c] : 0.f;
        vals[i] = v; s += v; s2 += v * v;
    }
#pragma unroll
    for (int o = 16; o; o >>= 1) {
        s  += __shfl_xor_sync(0xffffffffu, s,  o);
        s2 += __shfl_xor_sync(0xffffffffu, s2, o);
    }
    float m = s * (1.f / CD);
    float rstd = rsqrtf(s2 * (1.f / CD) - m * m + 1e-5f);
    __nv_bfloat16* y1 = g_a1  + (size_t)r * KP1;
    __nv_bfloat16* y2 = g_a1m + (size_t)r * KP1;
    const float* pbr = pb + (size_t)(r & 63) * CD;
#pragma unroll
    for (int i = 0; i < 6; i++) {
        int c = lane + i * 32;
        if (c < CD) {
            float v = (vals[i] - m) * rstd * g[c] + b[c];
            y1[c] = __float2bfloat16(v);
            y2[c] = __float2bfloat16(v + pbr[c]);
        } else {
            y1[c] = __float2bfloat16(0.f);
            y2[c] = __float2bfloat16(0.f);
        }
    }
}

__global__ void ln2_kernel(const float* __restrict__ g, const float* __restrict__ b) {
    int r = blockIdx.x * 8 + (threadIdx.x >> 5);
    int lane = threadIdx.x & 31;
    const float* xr = g_x1 + (size_t)r * CD;
    float vals[6], s = 0.f, s2 = 0.f;
#pragma unroll
    for (int i = 0; i < 6; i++) {
        int c = lane + i * 32;
        float v = (c < CD) ? xr[c] : 0.f;
        vals[i] = v; s += v; s2 += v * v;
    }
#pragma unroll
    for (int o = 16; o; o >>= 1) {
        s  += __shfl_xor_sync(0xffffffffu, s,  o);
        s2 += __shfl_xor_sync(0xffffffffu, s2, o);
    }
    float m = s * (1.f / CD);
    float rstd = rsqrtf(s2 * (1.f / CD) - m * m + 1e-5f);
    __nv_bfloat16* y = g_a2 + (size_t)r * KP1;
#pragma unroll
    for (int i = 0; i < 6; i++) {
        int c = lane + i * 32;
        float v = (c < CD) ? (vals[i] - m) * rstd * g[c] + b[c] : 0.f;
        y[c] = __float2bfloat16(v);
    }
}

// ------------------------- GEMM body (device fn, 3-stage cp.async ring) ----
#define SBUF 9216   // halves per buffer (128*72)
template<int EPI>
__device__ __forceinline__ void gemm_body(
    const __nv_bfloat16* __restrict__ A, const __nv_bfloat16* __restrict__ Bt,
    const float* __restrict__ bias, const float* __restrict__ bias2,
    float* __restrict__ outF, __nv_bfloat16* __restrict__ outH,
    const float* __restrict__ resid,
    int ldA, int K, int Nreal, int bx, int by, __nv_bfloat16* smp)
{
    const int tid = threadIdx.x, lane = tid & 31, wid = tid >> 5;
    const int wm = wid >> 2, wn = wid & 3;
    const int row0 = by * 128, col0 = bx * 128;

    float acc[4][4][4];
#pragma unroll
    for (int a = 0; a < 4; a++)
#pragma unroll
        for (int b = 0; b < 4; b++)
#pragma unroll
            for (int c = 0; c < 4; c++) acc[a][b][c] = 0.f;

    auto stage = [&](int buf, int k0) {
        __nv_bfloat16* dA = smp + buf * SBUF;
        __nv_bfloat16* dB = smp + 3 * SBUF + buf * SBUF;
#pragma unroll
        for (int i = 0; i < 4; i++) {
            int u = tid + i * 256;
            int r = u >> 3, s = u & 7;
            CP_ASYNC16(smem_u32(dA + r * 72 + s * 8),
                       A + (size_t)(row0 + r) * ldA + k0 + s * 8);
            CP_ASYNC16(smem_u32(dB + r * 72 + s * 8),
                       Bt + (size_t)(col0 + r) * ldA + k0 + s * 8);
        }
    };

    const int nC = K / 64;
    const int nst = (nC < 3) ? nC : 3;
    for (int i = 0; i < nst; i++) { stage(i, i * 64); CP_COMMIT(); }

    for (int c = 0; c < nC; c++) {
        int wg = nC - 1 - c; if (wg > 2) wg = 2;
        if (wg == 2) CP_WAIT2(); else if (wg == 1) CP_WAIT1(); else CP_WAIT0();
        __syncthreads();

        int buf = c % 3;
        __nv_bfloat16 (*sA)[72] = (__nv_bfloat16(*)[72])(smp + buf * SBUF);
        __nv_bfloat16 (*sB)[72] = (__nv_bfloat16(*)[72])(smp + 3 * SBUF + buf * SBUF);

#pragma unroll
        for (int ks = 0; ks < 4; ks++) {
            int kk = ks * 16;
            uint32_t af[4][4];
#pragma unroll
            for (int mt = 0; mt < 4; mt++) {
                int mr = wm * 64 + mt * 16 + (lane & 15);
                int mc = kk + ((lane >> 4) << 3);
                LDMATRIX_X4(af[mt][0], af[mt][1], af[mt][2], af[mt][3],
                            smem_u32(&sA[mr][mc]));
            }
            uint32_t bfr[4][2];
#pragma unroll
            for (int np = 0; np < 2; np++) {
                int nr = wn * 32 + np * 16 + (lane & 7) + ((lane >> 4) << 3);
                int nc = kk + (((lane >> 3) & 1) << 3);
                uint32_t r0, r1, r2, r3;
                LDMATRIX_X4(r0, r1, r2, r3, smem_u32(&sB[nr][nc]));
                bfr[np * 2][0] = r0;     bfr[np * 2][1] = r1;
                bfr[np * 2 + 1][0] = r2; bfr[np * 2 + 1][1] = r3;
            }
#pragma unroll
            for (int mt = 0; mt < 4; mt++)
#pragma unroll
                for (int nt = 0; nt < 4; nt++)
                    MMA16816(acc[mt][nt], af[mt], bfr[nt]);
        }
        __syncthreads();
        if (c + 3 < nC) { stage((c + 3) % 3, (c + 3) * 64); CP_COMMIT(); }
    }

    const int mbase = row0 + wm * 64, nbase = col0 + wn * 32;
#pragma unroll
    for (int mt = 0; mt < 4; mt++) {
#pragma unroll
        for (int half = 0; half < 2; half++) {
            int rr = mbase + mt * 16 + (lane >> 2) + half * 8;
            if (EPI == 0) {
                __nv_bfloat16* o = outH + (size_t)rr * C3;
#pragma unroll
                for (int nt = 0; nt < 4; nt++) {
                    int c = nbase + nt * 8 + ((lane & 3) << 1);
                    if (c < Nreal) {
                        __nv_bfloat162 h;
                        h.x = __float2bfloat16(acc[mt][nt][half * 2]     + bias[c]);
                        h.y = __float2bfloat16(acc[mt][nt][half * 2 + 1] + bias[c + 1]);
                        *(__nv_bfloat162*)(o + c) = h;
                    }
                }
            } else if (EPI == 1 || EPI == 3) {
                int gI = (EPI == 1) ? win2glob(rr) : rr;
                float* o = outF + (size_t)gI * CD;
                const float* rs = resid + (size_t)gI * CD;
#pragma unroll
                for (int nt = 0; nt < 4; nt++) {
                    int c = nbase + nt * 8 + ((lane & 3) << 1);
                    if (c < Nreal) {
                        float2 rv = *(const float2*)(rs + c);
                        float2 ov;
                        ov.x = rv.x + acc[mt][nt][half * 2]     + bias[c];
                        ov.y = rv.y + acc[mt][nt][half * 2 + 1] + bias[c + 1];
                        *(float2*)(o + c) = ov;
                    }
                }
            } else { // EPI == 2
                __nv_bfloat16* o = outH + (size_t)rr * KP2;
#pragma unroll
                for (int nt = 0; nt < 4; nt++) {
                    int c = nbase + nt * 8 + ((lane & 3) << 1);
                    if (c < 720) {
                        int n = c >> 1;
                        float u = acc[mt][nt][half * 2]     + bias[n];
                        float v = acc[mt][nt][half * 2 + 1] + bias2[n];
                        float ge = 0.5f * u * (1.f + erff(u * 0.7071067811865475f));
                        o[n] = __float2bfloat16(ge * v);
                    }
                }
            }
        }
    }
}

template<int EPI>
__global__ __launch_bounds__(256) void mma_gemm(
    const __nv_bfloat16* __restrict__ A, const __nv_bfloat16* __restrict__ Bt,
    const float* __restrict__ bias, const float* __restrict__ bias2,
    float* __restrict__ outF, __nv_bfloat16* __restrict__ outH,
    const float* __restrict__ resid, int ldA, int K, int Nreal)
{
    extern __shared__ __align__(16) __nv_bfloat16 smp[];
    gemm_body<EPI>(A, Bt, bias, bias2, outF, outH, resid, ldA, K, Nreal,
                   blockIdx.x, blockIdx.y, smp);
}

__global__ __launch_bounds__(256) void mma_gemm_qkv(
    const __nv_bfloat16* __restrict__ A0, const __nv_bfloat16* __restrict__ A1,
    const __nv_bfloat16* __restrict__ B0, const __nv_bfloat16* __restrict__ B1,
    const float* __restrict__ bias0, const float* __restrict__ bias1,
    __nv_bfloat16* __restrict__ out0, __nv_bfloat16* __restrict__ out1)
{
    extern __shared__ __align__(16) __nv_bfloat16 smp[];
    if (blockIdx.z == 0)
        gemm_body<0>(A0, B0, bias0, nullptr, nullptr, out0, nullptr,
                     KP1, KP1, C3, blockIdx.x, blockIdx.y, smp);
    else
        gemm_body<0>(A1, B1, bias1, nullptr, nullptr, out1, nullptr,
                     KP1, KP1, C3, blockIdx.x, blockIdx.y, smp);
}

// ------------------------- fused attention (self + mutual) -----------------
// self smem: Qb[128][40] Kb[128][40] Vt[32][136]  = 29184 B (bm read from global)
#define ASM_QB   0
#define ASM_KB   10240
#define ASM_VT   20480
// mutual smem: Qb[2][64][40] Kb[2][64][40] Vt[2][32][72] bm[64*68] = 38400 B
#define AMU_QB  0
#define AMU_KB  10240
#define AMU_VT  20480
#define AMU_BM  29696
#define ATT_SMEM 38400

__device__ __forceinline__ void attn_self_body(char* smc, int blk) {
    __nv_bfloat16 (*Qb)[40]  = (__nv_bfloat16(*)[40])(smc + ASM_QB);
    __nv_bfloat16 (*Kb)[40]  = (__nv_bfloat16(*)[40])(smc + ASM_KB);
    __nv_bfloat16 (*Vt)[136] = (__nv_bfloat16(*)[136])(smc + ASM_VT);

    int w = blk / NHEAD, h = blk % NHEAD;
    int tid = threadIdx.x, lane = tid & 31, wid = tid >> 5;
    const __nv_bfloat16* base = g_qkv_s + (size_t)w * 128 * C3;
    const uint32_t* bmw = (const uint32_t*)(g_bm + (size_t)blk * NMASK);

    // vectorized staging: 128 rows x 16 words (word 15 = zero pad)
    for (int idx = tid; idx < 128 * 16; idx += 128) {
        int m = idx >> 4, wd = idx & 15;
        const uint32_t* qr = (const uint32_t*)(base + (size_t)m * C3 + h * HDIM);
        const uint32_t* kr = (const uint32_t*)(base + (size_t)m * C3 + CD + h * HDIM);
        const uint32_t* vr = (const uint32_t*)(base + (size_t)m * C3 + 2 * CD + h * HDIM);
        uint32_t qv = (wd < 15) ? qr[wd] : 0u;
        uint32_t kv = (wd < 15) ? kr[wd] : 0u;
        ((uint32_t*)Qb[m])[wd] = qv;
        ((uint32_t*)Kb[m])[wd] = kv;
        if (wd < 15) {
            uint32_t vv = vr[wd];
            Vt[2 * wd][m]     = *(__nv_bfloat16*)&vv;
            Vt[2 * wd + 1][m] = *((__nv_bfloat16*)&vv + 1);
        } else {
            Vt[30][m] = __float2bfloat16(0.f);
            Vt[31][m] = __float2bfloat16(0.f);
        }
    }
    __syncthreads();

    float accS[2][16][4];
#pragma unroll
    for (int a = 0; a < 2; a++)
#pragma unroll
        for (int t = 0; t < 16; t++)
#pragma unroll
            for (int c = 0; c < 4; c++) accS[a][t][c] = 0.f;

#pragma unroll
    for (int ks = 0; ks < 2; ks++) {
        int kk = ks * 16;
        uint32_t af[2][4];
#pragma unroll
        for (int mt = 0; mt < 2; mt++) {
            int mr = wid * 32 + mt * 16 + (lane & 15);
            int mc = kk + ((lane >> 4) << 3);
            LDMATRIX_X4(af[mt][0], af[mt][1], af[mt][2], af[mt][3],
                        smem_u32(&Qb[mr][mc]));
        }
#pragma unroll
        for (int j = 0; j < 8; j++) {
            int nr = j * 16 + (lane & 7) + ((lane >> 4) << 3);
            int nc = kk + (((lane >> 3) & 1) << 3);
            uint32_t r0, r1, r2, r3;
            LDMATRIX_X4(r0, r1, r2, r3, smem_u32(&Kb[nr][nc]));
            uint32_t b0[2] = {r0, r1}, b1[2] = {r2, r3};
#pragma unroll
            for (int mt = 0; mt < 2; mt++) {
                MMA16816(accS[mt][2 * j],     af[mt], b0);
                MMA16816(accS[mt][2 * j + 1], af[mt], b1);
            }
        }
    }

    // softmax: bias+mask from global table; pack P in-place into accS[.][.][0..1]
    float linv[2][2];
#pragma unroll
    for (int mt = 0; mt < 2; mt++) {
        int row0 = wid * 32 + mt * 16 + (lane >> 2);
        int row1 = row0 + 8;
        float mx0 = -1e30f, mx1 = -1e30f;
#pragma unroll
        for (int t = 0; t < 16; t++) {
            int cw = t * 4 + (lane & 3);              // word index = col/2
            uint32_t u0 = bmw[row0 * 64 + cw];
            uint32_t u1 = bmw[row1 * 64 + cw];
            __nv_bfloat162 h0 = *(__nv_bfloat162*)&u0;
            __nv_bfloat162 h1 = *(__nv_bfloat162*)&u1;
            accS[mt][t][0] = accS[mt][t][0] * SCALE_F + __bfloat162float(h0.x);
            accS[mt][t][1] = accS[mt][t][1] * SCALE_F + __bfloat162float(h0.y);
            accS[mt][t][2] = accS[mt][t][2] * SCALE_F + __bfloat162float(h1.x);
            accS[mt][t][3] = accS[mt][t][3] * SCALE_F + __bfloat162float(h1.y);
            mx0 = fmaxf(mx0, fmaxf(accS[mt][t][0], accS[mt][t][1]));
            mx1 = fmaxf(mx1, fmaxf(accS[mt][t][2], accS[mt][t][3]));
        }
        mx0 = fmaxf(mx0, __shfl_xor_sync(0xffffffffu, mx0, 1));
        mx0 = fmaxf(mx0, __shfl_xor_sync(0xffffffffu, mx0, 2));
        mx1 = fmaxf(mx1, __shfl_xor_sync(0xffffffffu, mx1, 1));
        mx1 = fmaxf(mx1, __shfl_xor_sync(0xffffffffu, mx1, 2));
        float l0 = 0.f, l1 = 0.f;
#pragma unroll
        for (int t = 0; t < 16; t++) {
            float p0 = __expf(accS[mt][t][0] - mx0);
            float p1 = __expf(accS[mt][t][1] - mx0);
            float p2 = __expf(accS[mt][t][2] - mx1);
            float p3 = __expf(accS[mt][t][3] - mx1);
            l0 += p0 + p1; l1 += p2 + p3;
            __nv_bfloat162 q0 = __floats2bfloat162_rn(p0, p1);
            __nv_bfloat162 q1 = __floats2bfloat162_rn(p2, p3);
            accS[mt][t][0] = __uint_as_float(*(uint32_t*)&q0);
            accS[mt][t][1] = __uint_as_float(*(uint32_t*)&q1);
        }
        l0 += __shfl_xor_sync(0xffffffffu, l0, 1);
        l0 += __shfl_xor_sync(0xffffffffu, l0, 2);
        l1 += __shfl_xor_sync(0xffffffffu, l1, 1);
        l1 += __shfl_xor_sync(0xffffffffu, l1, 2);
        linv[mt][0] = 1.f / l0;
        linv[mt][1] = 1.f / l1;
    }

    float accO[2][4][4];
#pragma unroll
    for (int a = 0; a < 2; a++)
#pragma unroll
        for (int b = 0; b < 4; b++)
#pragma unroll
            for (int c = 0; c < 4; c++) accO[a][b][c] = 0.f;

#pragma unroll
    for (int ks = 0; ks < 8; ks++) {
        uint32_t bfr[4][2];
#pragma unroll
        for (int np = 0; np < 2; np++) {
            int nr = np * 16 + (lane & 7) + ((lane >> 4) << 3);
            int nc = ks * 16 + (((lane >> 3) & 1) << 3);
            uint32_t r0, r1, r2, r3;
            LDMATRIX_X4(r0, r1, r2, r3, smem_u32(&Vt[nr][nc]));
            bfr[np * 2][0] = r0;     bfr[np * 2][1] = r1;
            bfr[np * 2 + 1][0] = r2; bfr[np * 2 + 1][1] = r3;
        }
#pragma unroll
        for (int mt = 0; mt < 2; mt++) {
            uint32_t am[4] = {__float_as_uint(accS[mt][2 * ks][0]),
                              __float_as_uint(accS[mt][2 * ks][1]),
                              __float_as_uint(accS[mt][2 * ks + 1][0]),
                              __float_as_uint(accS[mt][2 * ks + 1][1])};
#pragma unroll
            for (int nt = 0; nt < 4; nt++)
                MMA16816(accO[mt][nt], am, bfr[nt]);
        }
    }

#pragma unroll
    for (int mt = 0; mt < 2; mt++) {
#pragma unroll
        for (int half = 0; half < 2; half++) {
            int row = wid * 32 + mt * 16 + (lane >> 2) + half * 8;
            float inv = linv[mt][half];
            __nv_bfloat16* o = g_xo + (size_t)(w * 128 + row) * KP2 + CD + h * HDIM;
#pragma unroll
            for (int nt = 0; nt < 4; nt++) {
                int col = nt * 8 + ((lane & 3) << 1);
                if (col < HDIM) {
                    __nv_bfloat162 hv;
                    hv.x = __float2bfloat16(accO[mt][nt][half * 2]     * inv);
                    hv.y = __float2bfloat16(accO[mt][nt][half * 2 + 1] * inv);
                    *(__nv_bfloat162*)(o + col) = hv;
                }
            }
        }
    }
}

__device__ __forceinline__ void attn_mut_body(char* smc, const float* __restrict__ mask,
                                              int blk) {
    __nv_bfloat16 (*Qb)[64][40] = (__nv_bfloat16(*)[64][40])(smc + AMU_QB);
    __nv_bfloat16 (*Kb)[64][40] = (__nv_bfloat16(*)[64][40])(smc + AMU_KB);
    __nv_bfloat16 (*Vt)[32][72] = (__nv_bfloat16(*)[32][72])(smc + AMU_VT);
    __nv_bfloat16* bm           = (__nv_bfloat16*)(smc + AMU_BM);  // stride 68

    int h = blk % NHEAD, w = blk / NHEAD;
    int tid = threadIdx.x, lane = tid & 31;
    int part = tid >> 6, ptid = tid & 63, wid2 = ptid >> 5;
    const __nv_bfloat16* base = g_qkv_m + (size_t)w * 128 * C3;
    int kvoff = part * 64;
    int qoff  = 64 - kvoff;

    for (int idx = ptid; idx < 64 * 16; idx += 64) {
        int m = idx >> 4, wd = idx & 15;
        const uint32_t* qr = (const uint32_t*)(base + (size_t)(qoff + m) * C3 + h * HDIM);
        const uint32_t* kr = (const uint32_t*)(base + (size_t)(kvoff + m) * C3 + CD + h * HDIM);
        const uint32_t* vr = (const uint32_t*)(base + (size_t)(kvoff + m) * C3 + 2 * CD + h * HDIM);
        uint32_t qv = (wd < 15) ? qr[wd] : 0u;
        uint32_t kv = (wd < 15) ? kr[wd] : 0u;
        ((uint32_t*)Qb[part][m])[wd] = qv;
        ((uint32_t*)Kb[part][m])[wd] = kv;
        if (wd < 15) {
            uint32_t vv = vr[wd];
            Vt[part][2 * wd][m]     = *(__nv_bfloat16*)&vv;
            Vt[part][2 * wd + 1][m] = *((__nv_bfloat16*)&vv + 1);
        } else {
            Vt[part][30][m] = __float2bfloat16(0.f);
            Vt[part][31][m] = __float2bfloat16(0.f);
        }
    }
    {
        const float* mk = mask + (size_t)w * NMASK;   // top-left 64x64 block
        for (int idx = tid; idx < 64 * 64; idx += 128) {
            int n = idx >> 6, m = idx & 63;
            bm[n * 68 + m] = __float2bfloat16(mk[n * 128 + m]);
        }
    }
    __syncthreads();

    float accS[2][8][4];
#pragma unroll
    for (int a = 0; a < 2; a++)
#pragma unroll
        for (int t = 0; t < 8; t++)
#pragma unroll
            for (int c = 0; c < 4; c++) accS[a][t][c] = 0.f;

#pragma unroll
    for (int ks = 0; ks < 2; ks++) {
        int kk = ks * 16;
        uint32_t af[2][4];
#pragma unroll
        for (int mt = 0; mt < 2; mt++) {
            int mr = wid2 * 32 + mt * 16 + (lane & 15);
            int mc = kk + ((lane >> 4) << 3);
            LDMATRIX_X4(af[mt][0], af[mt][1], af[mt][2], af[mt][3],
                        smem_u32(&Qb[part][mr][mc]));
        }
#pragma unroll
        for (int j = 0; j < 4; j++) {
            int nr = j * 16 + (lane & 7) + ((lane >> 4) << 3);
            int nc = kk + (((lane >> 3) & 1) << 3);
            uint32_t r0, r1, r2, r3;
            LDMATRIX_X4(r0, r1, r2, r3, smem_u32(&Kb[part][nr][nc]));
            uint32_t b0[2] = {r0, r1}, b1[2] = {r2, r3};
#pragma unroll
            for (int mt = 0; mt < 2; mt++) {
                MMA16816(accS[mt][2 * j],     af[mt], b0);
                MMA16816(accS[mt][2 * j + 1], af[mt], b1);
            }
        }
    }

    float linv[2][2];
#pragma unroll
    for (int mt = 0; mt < 2; mt++) {
        int row0 = wid2 * 32 + mt * 16 + (lane >> 2);
        int row1 = row0 + 8;
        float mx0 = -1e30f, mx1 = -1e30f;
#pragma unroll
        for (int t = 0; t < 8; t++) {
            int col = t * 8 + ((lane & 3) << 1);
            uint32_t u0 = *(const uint32_t*)(bm + row0 * 68 + col);
            uint32_t u1 = *(const uint32_t*)(bm + row1 * 68 + col);
            __nv_bfloat162 h0 = *(__nv_bfloat162*)&u0;
            __nv_bfloat162 h1 = *(__nv_bfloat162*)&u1;
            accS[mt][t][0] = accS[mt][t][0] * SCALE_F + __bfloat162float(h0.x);
            accS[mt][t][1] = accS[mt][t][1] * SCALE_F + __bfloat162float(h0.y);
            accS[mt][t][2] = accS[mt][t][2] * SCALE_F + __bfloat162float(h1.x);
            accS[mt][t][3] = accS[mt][t][3] * SCALE_F + __bfloat162float(h1.y);
            mx0 = fmaxf(mx0, fmaxf(accS[mt][t][0], accS[mt][t][1]));
            mx1 = fmaxf(mx1, fmaxf(accS[mt][t][2], accS[mt][t][3]));
        }
        mx0 = fmaxf(mx0, __shfl_xor_sync(0xffffffffu, mx0, 1));
        mx0 = fmaxf(mx0, __shfl_xor_sync(0xffffffffu, mx0, 2));
        mx1 = fmaxf(mx1, __shfl_xor_sync(0xffffffffu, mx1, 1));
        mx1 = fmaxf(mx1, __shfl_xor_sync(0xffffffffu, mx1, 2));
        float l0 = 0.f, l1 = 0.f;
#pragma unroll
        for (int t = 0; t < 8; t++) {
            float p0 = __expf(accS[mt][t][0] - mx0);
            float p1 = __expf(accS[mt][t][1] - mx0);
            float p2 = __expf(accS[mt][t][2] - mx1);
            float p3 = __expf(accS[mt][t][3] - mx1);
            l0 += p0 + p1; l1 += p2 + p3;
            __nv_bfloat162 q0 = __floats2bfloat162_rn(p0, p1);
            __nv_bfloat162 q1 = __floats2bfloat162_rn(p2, p3);
            accS[mt][t][0] = __uint_as_float(*(uint32_t*)&q0);
            accS[mt][t][1] = __uint_as_float(*(uint32_t*)&q1);
        }
        l0 += __shfl_xor_sync(0xffffffffu, l0, 1);
        l0 += __shfl_xor_sync(0xffffffffu, l0, 2);
        l1 += __shfl_xor_sync(0xffffffffu, l1, 1);
        l1 += __shfl_xor_sync(0xffffffffu, l1, 2);
        linv[mt][0] = 1.f / l0;
        linv[mt][1] = 1.f / l1;
    }

    float accO[2][4][4];
#pragma unroll
    for (int a = 0; a < 2; a++)
#pragma unroll
        for (int b2_ = 0; b2_ < 4; b2_++)
#pragma unroll
            for (int c = 0; c < 4; c++) accO[a][b2_][c] = 0.f;

#pragma unroll
    for (int ks = 0; ks < 4; ks++) {
        uint32_t bfr[4][2];
#pragma unroll
        for (int np = 0; np < 2; np++) {
            int nr = np * 16 + (lane & 7) + ((lane >> 4) << 3);
            int nc = ks * 16 + (((lane >> 3) & 1) << 3);
            uint32_t r0, r1, r2, r3;
            LDMATRIX_X4(r0, r1, r2, r3, smem_u32(&Vt[part][nr][nc]));
            bfr[np * 2][0] = r0;     bfr[np * 2][1] = r1;
            bfr[np * 2 + 1][0] = r2; bfr[np * 2 + 1][1] = r3;
        }
#pragma unroll
        for (int mt = 0; mt < 2; mt++) {
            uint32_t am[4] = {__float_as_uint(accS[mt][2 * ks][0]),
                              __float_as_uint(accS[mt][2 * ks][1]),
                              __float_as_uint(accS[mt][2 * ks + 1][0]),
                              __float_as_uint(accS[mt][2 * ks + 1][1])};
#pragma unroll
            for (int nt = 0; nt < 4; nt++)
                MMA16816(accO[mt][nt], am, bfr[nt]);
        }
    }

#pragma unroll
    for (int mt = 0; mt < 2; mt++) {
#pragma unroll
        for (int half = 0; half < 2; half++) {
            int row = wid2 * 32 + mt * 16 + (lane >> 2) + half * 8;
            float inv = linv[mt][half];
            __nv_bfloat16* o = g_xo + (size_t)(w * 128 + part * 64 + row) * KP2 + h * HDIM;
#pragma unroll
            for (int nt = 0; nt < 4; nt++) {
                int col = nt * 8 + ((lane & 3) << 1);
                if (col < HDIM) {
                    __nv_bfloat162 hv;
                    hv.x = __float2bfloat16(accO[mt][nt][half * 2]     * inv);
                    hv.y = __float2bfloat16(accO[mt][nt][half * 2 + 1] * inv);
                    *(__nv_bfloat162*)(o + col) = hv;
                }
            }
        }
    }
}

__global__ __launch_bounds__(128) void attn_fused(const float* __restrict__ mask) {
    extern __shared__ __align__(16) char smc[];
    int blk = blockIdx.x;
    if (blk < NWIN * NHEAD) attn_self_body(smc, blk);
    else                    attn_mut_body(smc, mask, blk - NWIN * NHEAD);
}

// ---------------------------------------------------------------------------
extern "C" void kernel_launch(void* const* d_in, const int* in_sizes, int n_in,
                              void* d_out, int out_size) {
    const float* x          = (const float*)d_in[0];
    const float* mask       = (const float*)d_in[1];
    const float* g1         = (const float*)d_in[2];
    const float* b1         = (const float*)d_in[3];
    const float* g2         = (const float*)d_in[4];
    const float* b2         = (const float*)d_in[5];
    const float* w_qkv_self = (const float*)d_in[6];
    const float* b_qkv_self = (const float*)d_in[7];
    const float* w_qkv_mut  = (const float*)d_in[8];
    const float* b_qkv_mut  = (const float*)d_in[9];
    const float* rpb_table  = (const float*)d_in[10];
    const float* pos_bias   = (const float*)d_in[11];
    const float* w_proj     = (const float*)d_in[12];
    const float* b_proj     = (const float*)d_in[13];
    const float* w_fc11     = (const float*)d_in[14];
    const float* b_fc11     = (const float*)d_in[15];
    const float* w_fc12     = (const float*)d_in[16];
    const float* b_fc12     = (const float*)d_in[17];
    const float* w_fc2      = (const float*)d_in[18];
    const float* b_fc2      = (const float*)d_in[19];
    const int*   rpi        = (const int*)d_in[20];
    float* out = (float*)d_out;

    __nv_bfloat16 *p_a1, *p_a1m, *p_qs, *p_qm, *p_xo, *p_a2, *p_hid;
    __nv_bfloat16 *p_wqs, *p_wqm, *p_wpr, *p_wmix, *p_wf2;
    float *p_x1;
    cudaGetSymbolAddress((void**)&p_a1,  g_a1);
    cudaGetSymbolAddress((void**)&p_a1m, g_a1m);
    cudaGetSymbolAddress((void**)&p_qs,  g_qkv_s);
    cudaGetSymbolAddress((void**)&p_qm,  g_qkv_m);
    cudaGetSymbolAddress((void**)&p_xo,  g_xo);
    cudaGetSymbolAddress((void**)&p_a2,  g_a2);
    cudaGetSymbolAddress((void**)&p_hid, g_hid);
    cudaGetSymbolAddress((void**)&p_x1,  g_x1);
    cudaGetSymbolAddress((void**)&p_wqs, g_wqs);
    cudaGetSymbolAddress((void**)&p_wqm, g_wqm);
    cudaGetSymbolAddress((void**)&p_wpr, g_wpr);
    cudaGetSymbolAddress((void**)&p_wmix,g_wmix);
    cudaGetSymbolAddress((void**)&p_wf2, g_wf2);

    cudaFuncSetAttribute(attn_fused,
                         cudaFuncAttributeMaxDynamicSharedMemorySize, ATT_SMEM);

    int gemm_smem = 6 * SBUF * 2;   // 110592 B (A[3] + B[3])
    cudaFuncSetAttribute(mma_gemm_qkv, cudaFuncAttributeMaxDynamicSharedMemorySize, gemm_smem);
    cudaFuncSetAttribute(mma_gemm<1>, cudaFuncAttributeMaxDynamicSharedMemorySize, gemm_smem);
    cudaFuncSetAttribute(mma_gemm<2>, cudaFuncAttributeMaxDynamicSharedMemorySize, gemm_smem);
    cudaFuncSetAttribute(mma_gemm<3>, cudaFuncAttributeMaxDynamicSharedMemorySize, gemm_smem);

    // 1) merged prep (incl. combined bias+mask table)
    prep_all<<<(int)((PREP_TOTAL + 255) / 256), 256>>>(
        rpb_table, rpi, mask, w_qkv_self, w_qkv_mut, w_proj, w_fc2, w_fc11, w_fc12);
    // 2) LN1 + roll + window partition
    ln1_kernel<<<NTOK / 8, 256>>>(x, g1, b1, pos_bias);
    // 3) both qkv GEMMs in one launch
    mma_gemm_qkv<<<dim3(5, NTOK / 128, 2), 256, gemm_smem>>>(
        p_a1, p_a1m, p_wqs, p_wqm, b_qkv_self, b_qkv_mut, p_qs, p_qm);
    // 4) fused attention (self + mutual)
    attn_fused<<<2 * NWIN * NHEAD, 128, ATT_SMEM>>>(mask);
    // 5) proj (+win_rev+roll+resid)
    mma_gemm<1><<<dim3(2, NTOK / 128), 256, gemm_smem>>>(p_xo, p_wpr, b_proj, nullptr,
                                              p_x1, nullptr, x, KP2, KP2, CD);
    // 6) LN2
    ln2_kernel<<<NTOK / 8, 256>>>(g2, b2);
    // 7) fc1 (fused GEGLU)
    mma_gemm<2><<<dim3(6, NTOK / 128), 256, gemm_smem>>>(p_a2, p_wmix, b_fc11, b_fc12,
                                              nullptr, p_hid, nullptr, KP1, KP1, 720);
    // 8) fc2 + residual
    mma_gemm<3><<<dim3(2, NTOK / 128), 256, gemm_smem>>>(p_hid, p_wf2, b_fc2, nullptr,
                                              out, nullptr, p_x1, KP2, KP2, CD);
    (void)in_sizes; (void)n_in; (void)out_size;
}